// round 3
// baseline (speedup 1.0000x reference)
#include <cuda_runtime.h>

#define NN 50000
#define FF 16
#define TH 10
#define TOUT 10
#define EE 800000
#define HH 64
#define NSTEPS 40
#define NF (NN*FF)
#define NF4 (NF/4)

// ---------------- scratch (static device globals; no allocs) ----------------
__device__ int    g_cnt[NN];
__device__ int    g_rowptr[NN + 1];
__device__ int    g_cursor[NN];
__device__ int    g_srcs[EE];
__device__ __align__(16) float4 g_eas[EE];
__device__ __align__(16) float  g_U[NN * 64];   // x @ W1m[0:16]      (gathered by src)
__device__ __align__(16) float  g_V[NN * 64];   // x @ W1m[16:32]+b1m (per-dst)
__device__ __align__(16) float  g_W[NN * 64];   // x @ W1n[0:16]      (per-node)
__device__ __align__(16) float  g_augp[NN * HH];
__device__ __align__(16) float4 g_x4[NF4];
__device__ __align__(16) float4 g_k4[6][NF4];
__device__ __align__(16) float4 g_ys4[TOUT][NF4];
__device__ float  g_M[HH * HH];   // W2m @ W1n_agg
__device__ float  g_c[HH];        // b2m @ W1n_agg

__constant__ float c_A[6][5] = {
    {0.f, 0.f, 0.f, 0.f, 0.f},
    {0.2f, 0.f, 0.f, 0.f, 0.f},
    {3.f/40.f, 9.f/40.f, 0.f, 0.f, 0.f},
    {44.f/45.f, -56.f/15.f, 32.f/9.f, 0.f, 0.f},
    {19372.f/6561.f, -25360.f/2187.f, 64448.f/6561.f, -212.f/729.f, 0.f},
    {9017.f/3168.f, -355.f/33.f, 46732.f/5247.f, 49.f/176.f, -5103.f/18656.f}
};
__constant__ float c_C[6] = {0.f, 0.2f, 0.3f, 0.8f, 8.f/9.f, 1.f};
__constant__ float c_B[6] = {35.f/384.f, 0.f, 500.f/1113.f, 125.f/192.f, -2187.f/6784.f, 11.f/84.f};

__device__ __forceinline__ float tanh_fast(float x) {
    float ax = fabsf(x);
    float e  = __expf(ax + ax);
    float y  = 1.f - __fdividef(2.f, e + 1.f);
    return copysignf(y, x);
}

__device__ __forceinline__ float4 f4add(float4 a, float4 b) {
    return make_float4(a.x+b.x, a.y+b.y, a.z+b.z, a.w+b.w);
}
__device__ __forceinline__ float4 f4fma(float s, float4 a, float4 b) {
    return make_float4(fmaf(s,a.x,b.x), fmaf(s,a.y,b.y), fmaf(s,a.z,b.z), fmaf(s,a.w,b.w));
}

// ---------------- precompute ----------------
__global__ void k_zero() {
    int i = blockIdx.x * blockDim.x + threadIdx.x;
    if (i < NN) g_cnt[i] = 0;
}
__global__ void k_hist(const int* __restrict__ eidx) {
    int e = blockIdx.x * blockDim.x + threadIdx.x;
    if (e < EE) atomicAdd(&g_cnt[eidx[EE + e]], 1);
}
__global__ void k_scan() {
    __shared__ int sh[1024];
    __shared__ int carry_s;
    int t = threadIdx.x;
    if (t == 0) carry_s = 0;
    __syncthreads();
    for (int base = 0; base < NN; base += 1024) {
        int v = (base + t < NN) ? g_cnt[base + t] : 0;
        int x = v;
        for (int off = 1; off < 1024; off <<= 1) {
            sh[t] = x; __syncthreads();
            if (t >= off) x += sh[t - off];
            __syncthreads();
        }
        int cprev = carry_s;
        int excl  = cprev + x - v;
        if (base + t < NN) { g_rowptr[base + t] = excl; g_cursor[base + t] = excl; }
        __syncthreads();
        if (t == 1023) carry_s = cprev + x;
        __syncthreads();
    }
    if (t == 0) g_rowptr[NN] = carry_s;
}
__global__ void k_scatter(const int* __restrict__ eidx, const float* __restrict__ eattr) {
    int e = blockIdx.x * blockDim.x + threadIdx.x;
    if (e >= EE) return;
    int src = eidx[e];
    int dst = eidx[EE + e];
    int pos = atomicAdd(&g_cursor[dst], 1);
    g_srcs[pos] = src;
    g_eas[pos]  = reinterpret_cast<const float4*>(eattr)[e];
}
__global__ void k_init_x(const float* __restrict__ x_hist) {
    int i = blockIdx.x * blockDim.x + threadIdx.x;
    if (i < NF4) g_x4[i] = reinterpret_cast<const float4*>(x_hist)[(TH - 1) * NF4 + i];
}
__global__ void k_M(const float* __restrict__ W2m, const float* __restrict__ W1n,
                    const float* __restrict__ b2m) {
    int tid = blockIdx.x * blockDim.x + threadIdx.x;
    if (tid < HH * HH) {
        int j = tid >> 6, i = tid & 63;
        float s = 0.f;
        #pragma unroll
        for (int k = 0; k < 16; k++) s += W2m[j * 16 + k] * W1n[(16 + k) * 64 + i];
        g_M[tid] = s;
    }
    if (tid < HH) {
        float s = 0.f;
        #pragma unroll
        for (int k = 0; k < 16; k++) s += b2m[k] * W1n[(16 + k) * 64 + tid];
        g_c[tid] = s;
    }
}
__global__ void k_aug(const float* __restrict__ xh, const float* __restrict__ xm,
                      const float* __restrict__ W1n, const float* __restrict__ b1n) {
    __shared__ float aug_s[8][176];
    int tid = threadIdx.x, lane = tid & 31, w = tid >> 5;
    int n = blockIdx.x * 8 + w;
    if (n >= NN) return;
    if (lane < 16) {
        int f = lane;
        float xv[TH], mv[TH];
        float sx = 0.f, sm = 0.f;
        #pragma unroll
        for (int t = 0; t < TH; t++) {
            xv[t] = xh[t * NF + n * FF + f];
            mv[t] = xm[t * NN + n];
            sx += xv[t] * mv[t];
            sm += mv[t];
        }
        float cnt  = fmaxf(sm, 1.f);
        float mean = sx / cnt;
        float var = 0.f;
        #pragma unroll
        for (int t = 0; t < TH; t++) {
            float d = xv[t] - mean;
            var += d * d * mv[t];
        }
        var /= cnt;
        #pragma unroll
        for (int t = 0; t < TH - 1; t++)
            aug_s[w][t * 16 + f] = (xv[t + 1] - xv[t]) * mv[t + 1] * mv[t];
        aug_s[w][144 + f] = mean;
        aug_s[w][160 + f] = var;
    }
    __syncwarp();
    int i0 = 2 * lane;
    float acc0 = b1n[i0], acc1 = b1n[i0 + 1];
    for (int a = 0; a < 176; a++) {
        float av = aug_s[w][a];
        float2 wv = *reinterpret_cast<const float2*>(&W1n[(32 + a) * 64 + i0]);
        acc0 += av * wv.x;
        acc1 += av * wv.y;
    }
    g_augp[n * HH + i0]     = acc0;
    g_augp[n * HH + i0 + 1] = acc1;
}

// ---------------- per-stage: projection (fused with previous step's combine at stage 0) ----
// 6 warps; warp w handles 32 cols of one of U/V/W; one column per lane (16 weight regs).
// 128 nodes per block.
__global__ void __launch_bounds__(192)
k_proj(const float* __restrict__ t_arr, const float* __restrict__ W1m,
       const float* __restrict__ W1n, const float* __restrict__ b1m,
       int stage, int step) {
    __shared__ float4 xi_s[128 * 4];
    int tid = threadIdx.x, lane = tid & 31, w = tid >> 5;
    int nb = blockIdx.x * 128;
    int nmax = NN - nb; if (nmax > 128) nmax = 128;

    int iv = step >> 2;
    float dt_int = (t_arr[iv + 1] - t_arr[iv]) * 0.25f;

    // ---- build xi (and fused combine of previous step when stage==0, step>0) ----
    for (int i = tid; i < nmax * 4; i += 192) {
        int g = nb * 4 + i;
        float4 xv = g_x4[g];
        float4 out;
        if (stage == 0) {
            if (step > 0) {
                int pstep = step - 1;
                int piv = pstep >> 2;
                float pdt = (t_arr[piv + 1] - t_arr[piv]) * 0.25f;
                float4 s = make_float4(0.f, 0.f, 0.f, 0.f);
                s = f4fma(c_B[0], g_k4[0][g], s);
                s = f4fma(c_B[2], g_k4[2][g], s);
                s = f4fma(c_B[3], g_k4[3][g], s);
                s = f4fma(c_B[4], g_k4[4][g], s);
                s = f4fma(c_B[5], g_k4[5][g], s);
                out = f4fma(pdt, s, xv);
                g_x4[g] = out;
                if ((pstep & 3) == 3) g_ys4[piv][g] = out;
            } else {
                out = xv;
            }
        } else {
            float4 s = make_float4(0.f, 0.f, 0.f, 0.f);
            #pragma unroll
            for (int j = 0; j < 5; j++)
                if (j < stage) s = f4fma(c_A[stage][j], g_k4[j][g], s);
            out = f4fma(dt_int, s, xv);
        }
        xi_s[i] = out;
    }
    __syncthreads();

    // ---- weights for my column ----
    int coff = lane + 32 * (w & 1);
    const float* wsrc;
    float* outp;
    float bias = 0.f;
    if (w < 2)       { wsrc = W1m;           outp = g_U; }
    else if (w < 4)  { wsrc = W1m + 16 * 64; outp = g_V; bias = b1m[coff]; }
    else             { wsrc = W1n;           outp = g_W; }
    float wreg[16];
    #pragma unroll
    for (int f = 0; f < 16; f++) wreg[f] = wsrc[f * 64 + coff];

    for (int nl = 0; nl < nmax; nl++) {
        float4 a0 = xi_s[nl * 4 + 0];
        float4 a1 = xi_s[nl * 4 + 1];
        float4 a2 = xi_s[nl * 4 + 2];
        float4 a3 = xi_s[nl * 4 + 3];
        float acc = bias;
        acc = fmaf(a0.x, wreg[0],  acc); acc = fmaf(a0.y, wreg[1],  acc);
        acc = fmaf(a0.z, wreg[2],  acc); acc = fmaf(a0.w, wreg[3],  acc);
        acc = fmaf(a1.x, wreg[4],  acc); acc = fmaf(a1.y, wreg[5],  acc);
        acc = fmaf(a1.z, wreg[6],  acc); acc = fmaf(a1.w, wreg[7],  acc);
        acc = fmaf(a2.x, wreg[8],  acc); acc = fmaf(a2.y, wreg[9],  acc);
        acc = fmaf(a2.z, wreg[10], acc); acc = fmaf(a2.w, wreg[11], acc);
        acc = fmaf(a3.x, wreg[12], acc); acc = fmaf(a3.y, wreg[13], acc);
        acc = fmaf(a3.z, wreg[14], acc); acc = fmaf(a3.w, wreg[15], acc);
        outp[(nb + nl) * 64 + coff] = acc;
    }
}

// ---------------- per-stage: edge aggregation + node MLP ----------------
__global__ void __launch_bounds__(256)
k_node(const float* __restrict__ t_arr, const float* __restrict__ W1m,
       const float* __restrict__ W1n, const float* __restrict__ W2n,
       const float* __restrict__ b2n, int stage, int step) {
    __shared__ float M_s[HH * HH];
    __shared__ float wt_s[64], c_s[64];
    __shared__ float W2n_s[64 * 16];
    __shared__ float b2n_s[16];
    __shared__ float hbuf[8][64];

    int tid = threadIdx.x, lane = tid & 31, w = tid >> 5;
    for (int i = tid; i < HH * HH; i += 256) M_s[i] = g_M[i];
    for (int i = tid; i < 64; i += 256) { wt_s[i] = W1n[208 * 64 + i]; c_s[i] = g_c[i]; }
    for (int i = tid; i < 1024; i += 256) W2n_s[i] = W2n[i];
    if (tid < 16) b2n_s[tid] = b2n[tid];
    __syncthreads();

    int iv = step >> 2;
    float dt_int = (t_arr[iv + 1] - t_arr[iv]) * 0.25f;
    float ti = t_arr[iv] + (float)(step & 3) * dt_int + c_C[stage] * dt_int;

    // W1c columns (2*lane, 2*lane+1) for the 4 edge-attr rows
    float2 wc0 = *reinterpret_cast<const float2*>(&W1m[32 * 64 + 2 * lane]);
    float2 wc1 = *reinterpret_cast<const float2*>(&W1m[33 * 64 + 2 * lane]);
    float2 wc2 = *reinterpret_cast<const float2*>(&W1m[34 * 64 + 2 * lane]);
    float2 wc3 = *reinterpret_cast<const float2*>(&W1m[35 * 64 + 2 * lane]);

    for (int rep = 0; rep < 8; rep++) {
        int n = blockIdx.x * 64 + rep * 8 + w;
        if (n >= NN) continue;   // warp-uniform
        int rs = g_rowptr[n], re = g_rowptr[n + 1];
        float2 vv = *reinterpret_cast<const float2*>(&g_V[n * 64 + 2 * lane]);
        float hs0 = 0.f, hs1 = 0.f;

        for (int base = rs; base < re; base += 32) {
            int cnt = re - base; if (cnt > 32) cnt = 32;
            int sv = (lane < cnt) ? __ldg(&g_srcs[base + lane]) : 0;
            // depth-2 pipeline over edges in this chunk
            float2 u0 = make_float2(0.f, 0.f), u1 = make_float2(0.f, 0.f);
            float4 e0 = make_float4(0.f, 0.f, 0.f, 0.f), e1 = e0;
            int s0 = __shfl_sync(0xffffffffu, sv, 0);
            u0 = *reinterpret_cast<const float2*>(&g_U[s0 * 64 + 2 * lane]);
            e0 = g_eas[base];
            if (cnt > 1) {
                int s1 = __shfl_sync(0xffffffffu, sv, 1);
                u1 = *reinterpret_cast<const float2*>(&g_U[s1 * 64 + 2 * lane]);
                e1 = g_eas[base + 1];
            }
            for (int j = 0; j < cnt; j++) {
                float2 uc = u0; float4 ec = e0;
                u0 = u1; e0 = e1;
                if (j + 2 < cnt) {
                    int s2 = __shfl_sync(0xffffffffu, sv, j + 2);
                    u1 = *reinterpret_cast<const float2*>(&g_U[s2 * 64 + 2 * lane]);
                    e1 = g_eas[base + j + 2];
                }
                float p0 = uc.x + vv.x + ec.x * wc0.x + ec.y * wc1.x + ec.z * wc2.x + ec.w * wc3.x;
                float p1 = uc.y + vv.y + ec.x * wc0.y + ec.y * wc1.y + ec.z * wc2.y + ec.w * wc3.y;
                hs0 += tanh_fast(p0);
                hs1 += tanh_fast(p1);
            }
        }

        hbuf[w][2 * lane] = hs0; hbuf[w][2 * lane + 1] = hs1;
        __syncwarp();

        float deg = (float)(re - rs);
        float2 ww = *reinterpret_cast<const float2*>(&g_W[n * 64 + 2 * lane]);
        float2 ap = *reinterpret_cast<const float2*>(&g_augp[n * HH + 2 * lane]);
        float a0 = ww.x + deg * c_s[2 * lane]     + ti * wt_s[2 * lane]     + ap.x;
        float a1 = ww.y + deg * c_s[2 * lane + 1] + ti * wt_s[2 * lane + 1] + ap.y;
        #pragma unroll 4
        for (int j = 0; j < 64; j++) {
            float hj = hbuf[w][j];
            float2 mv = *reinterpret_cast<const float2*>(&M_s[j * 64 + 2 * lane]);
            a0 = fmaf(hj, mv.x, a0);
            a1 = fmaf(hj, mv.y, a1);
        }
        float h20 = tanh_fast(a0), h21 = tanh_fast(a1);
        __syncwarp();
        hbuf[w][2 * lane] = h20; hbuf[w][2 * lane + 1] = h21;
        __syncwarp();

        // 64x16 output matmul: full warp, split j-range, shfl reduce
        {
            int colc = lane & 15;
            int j0 = (lane >> 4) * 32;
            float acc = 0.f;
            #pragma unroll 8
            for (int j = j0; j < j0 + 32; j++)
                acc = fmaf(hbuf[w][j], W2n_s[j * 16 + colc], acc);
            acc += __shfl_xor_sync(0xffffffffu, acc, 16);
            if (lane < 16)
                reinterpret_cast<float*>(g_k4[stage])[n * 16 + lane] = acc + b2n_s[lane];
        }
        __syncwarp();
    }
}

__global__ void k_combine_final(const float* __restrict__ t_arr, int step) {
    int g = blockIdx.x * blockDim.x + threadIdx.x;
    if (g >= NF4) return;
    int iv = step >> 2;
    float dt_int = (t_arr[iv + 1] - t_arr[iv]) * 0.25f;
    float4 s = make_float4(0.f, 0.f, 0.f, 0.f);
    s = f4fma(c_B[0], g_k4[0][g], s);
    s = f4fma(c_B[2], g_k4[2][g], s);
    s = f4fma(c_B[3], g_k4[3][g], s);
    s = f4fma(c_B[4], g_k4[4][g], s);
    s = f4fma(c_B[5], g_k4[5][g], s);
    float4 xn = f4fma(dt_int, s, g_x4[g]);
    g_x4[g] = xn;
    if ((step & 3) == 3) g_ys4[iv][g] = xn;
}

__global__ void k_out(const int* __restrict__ midx, float4* __restrict__ out) {
    int idx = blockIdx.x * blockDim.x + threadIdx.x;
    if (idx >= TOUT * NF4) return;
    int r = idx / NF4;
    out[idx] = g_ys4[midx[r]][idx - r * NF4];
}

// ---------------- launch ----------------
extern "C" void kernel_launch(void* const* d_in, const int* in_sizes, int n_in,
                              void* d_out, int out_size) {
    const float* x_hist = (const float*)d_in[0];
    const float* x_mask = (const float*)d_in[1];
    const int*   eidx   = (const int*)  d_in[2];
    const float* eattr  = (const float*)d_in[3];
    const float* t_arr  = (const float*)d_in[4];
    const int*   midx   = (const int*)  d_in[5];
    const float* W1m = (const float*)d_in[6];
    const float* b1m = (const float*)d_in[7];
    const float* W2m = (const float*)d_in[8];
    const float* b2m = (const float*)d_in[9];
    const float* W1n = (const float*)d_in[10];
    const float* b1n = (const float*)d_in[11];
    const float* W2n = (const float*)d_in[12];
    const float* b2n = (const float*)d_in[13];
    float4* out = (float4*)d_out;

    k_zero   <<<(NN + 255) / 256, 256>>>();
    k_hist   <<<(EE + 255) / 256, 256>>>(eidx);
    k_scan   <<<1, 1024>>>();
    k_scatter<<<(EE + 255) / 256, 256>>>(eidx, eattr);
    k_init_x <<<(NF4 + 255) / 256, 256>>>(x_hist);
    k_M      <<<(HH * HH + 255) / 256, 256>>>(W2m, W1n, b2m);
    k_aug    <<<(NN + 7) / 8, 256>>>(x_hist, x_mask, W1n, b1n);

    for (int step = 0; step < NSTEPS; step++) {
        for (int stage = 0; stage < 6; stage++) {
            k_proj<<<(NN + 127) / 128, 192>>>(t_arr, W1m, W1n, b1m, stage, step);
            k_node<<<(NN + 63) / 64, 256>>>(t_arr, W1m, W1n, W2n, b2n, stage, step);
        }
    }
    k_combine_final<<<(NF4 + 255) / 256, 256>>>(t_arr, NSTEPS - 1);
    k_out<<<(TOUT * NF4 + 255) / 256, 256>>>(midx, out);
}

// round 6
// speedup vs baseline: 1.3908x; 1.3908x over previous
#include <cuda_runtime.h>

#define NN 50000
#define FF 16
#define TH 10
#define TOUT 10
#define EE 800000
#define HH 64
#define NSTEPS 40
#define NF (NN*FF)
#define NF4 (NF/4)

// ---------------- scratch (static device globals; no allocs) ----------------
__device__ int    g_cnt[NN];
__device__ int    g_rowptr[NN + 1];
__device__ int    g_cursor[NN];
__device__ int    g_srcs[EE];
__device__ __align__(16) float4 g_eas[EE];
__device__ __align__(16) float  g_U[NN * 64];   // xi @ W1m[0:16]      (gathered by src)
__device__ __align__(16) float  g_V[NN * 64];   // xi @ W1m[16:32]+b1m (per-dst)
__device__ __align__(16) float  g_W[NN * 64];   // xi @ W1n[0:16]      (per-node)
__device__ __align__(16) float  g_augp[NN * HH];
__device__ __align__(16) float4 g_x4[NF4];
__device__ __align__(16) float4 g_k4[6][NF4];
__device__ __align__(16) float4 g_ys4[TOUT][NF4];
__device__ float  g_M[HH * HH];   // W2m @ W1n_agg
__device__ float  g_c[HH];        // b2m @ W1n_agg

__constant__ float c_A[6][5] = {
    {0.f, 0.f, 0.f, 0.f, 0.f},
    {0.2f, 0.f, 0.f, 0.f, 0.f},
    {3.f/40.f, 9.f/40.f, 0.f, 0.f, 0.f},
    {44.f/45.f, -56.f/15.f, 32.f/9.f, 0.f, 0.f},
    {19372.f/6561.f, -25360.f/2187.f, 64448.f/6561.f, -212.f/729.f, 0.f},
    {9017.f/3168.f, -355.f/33.f, 46732.f/5247.f, 49.f/176.f, -5103.f/18656.f}
};
__constant__ float c_C[6] = {0.f, 0.2f, 0.3f, 0.8f, 8.f/9.f, 1.f};
__constant__ float c_B[6] = {35.f/384.f, 0.f, 500.f/1113.f, 125.f/192.f, -2187.f/6784.f, 11.f/84.f};

// exact-ish tanh (2 MUFU) for the output layer
__device__ __forceinline__ float tanh_fast(float x) {
    float ax = fabsf(x);
    float e  = __expf(ax + ax);
    float y  = 1.f - __fdividef(2.f, e + 1.f);
    return copysignf(y, x);
}
// HW tanh (1 MUFU) for the edge layer
__device__ __forceinline__ float tanha(float x) {
    float y;
    asm("tanh.approx.f32 %0, %1;" : "=f"(y) : "f"(x));
    return y;
}

__device__ __forceinline__ float4 f4fma(float s, float4 a, float4 b) {
    return make_float4(fmaf(s,a.x,b.x), fmaf(s,a.y,b.y), fmaf(s,a.z,b.z), fmaf(s,a.w,b.w));
}

// ---------------- precompute ----------------
__global__ void k_zero() {
    int i = blockIdx.x * blockDim.x + threadIdx.x;
    if (i < NN) g_cnt[i] = 0;
}
__global__ void k_hist(const int* __restrict__ eidx) {
    int e = blockIdx.x * blockDim.x + threadIdx.x;
    if (e < EE) atomicAdd(&g_cnt[eidx[EE + e]], 1);
}
__global__ void k_scan() {
    __shared__ int sh[1024];
    __shared__ int carry_s;
    int t = threadIdx.x;
    if (t == 0) carry_s = 0;
    __syncthreads();
    for (int base = 0; base < NN; base += 1024) {
        int v = (base + t < NN) ? g_cnt[base + t] : 0;
        int x = v;
        for (int off = 1; off < 1024; off <<= 1) {
            sh[t] = x; __syncthreads();
            if (t >= off) x += sh[t - off];
            __syncthreads();
        }
        int cprev = carry_s;
        int excl  = cprev + x - v;
        if (base + t < NN) { g_rowptr[base + t] = excl; g_cursor[base + t] = excl; }
        __syncthreads();
        if (t == 1023) carry_s = cprev + x;
        __syncthreads();
    }
    if (t == 0) g_rowptr[NN] = carry_s;
}
__global__ void k_scatter(const int* __restrict__ eidx, const float* __restrict__ eattr) {
    int e = blockIdx.x * blockDim.x + threadIdx.x;
    if (e >= EE) return;
    int src = eidx[e];
    int dst = eidx[EE + e];
    int pos = atomicAdd(&g_cursor[dst], 1);
    g_srcs[pos] = src;
    g_eas[pos]  = reinterpret_cast<const float4*>(eattr)[e];
}
__global__ void k_init_x(const float* __restrict__ x_hist) {
    int i = blockIdx.x * blockDim.x + threadIdx.x;
    if (i < NF4) g_x4[i] = reinterpret_cast<const float4*>(x_hist)[(TH - 1) * NF4 + i];
}
__global__ void k_M(const float* __restrict__ W2m, const float* __restrict__ W1n,
                    const float* __restrict__ b2m) {
    int tid = blockIdx.x * blockDim.x + threadIdx.x;
    if (tid < HH * HH) {
        int j = tid >> 6, i = tid & 63;
        float s = 0.f;
        #pragma unroll
        for (int k = 0; k < 16; k++) s += W2m[j * 16 + k] * W1n[(16 + k) * 64 + i];
        g_M[tid] = s;
    }
    if (tid < HH) {
        float s = 0.f;
        #pragma unroll
        for (int k = 0; k < 16; k++) s += b2m[k] * W1n[(16 + k) * 64 + tid];
        g_c[tid] = s;
    }
}
__global__ void k_aug(const float* __restrict__ xh, const float* __restrict__ xm,
                      const float* __restrict__ W1n, const float* __restrict__ b1n) {
    __shared__ float aug_s[8][176];
    int tid = threadIdx.x, lane = tid & 31, w = tid >> 5;
    int n = blockIdx.x * 8 + w;
    if (n >= NN) return;
    if (lane < 16) {
        int f = lane;
        float xv[TH], mv[TH];
        float sx = 0.f, sm = 0.f;
        #pragma unroll
        for (int t = 0; t < TH; t++) {
            xv[t] = xh[t * NF + n * FF + f];
            mv[t] = xm[t * NN + n];
            sx += xv[t] * mv[t];
            sm += mv[t];
        }
        float cnt  = fmaxf(sm, 1.f);
        float mean = sx / cnt;
        float var = 0.f;
        #pragma unroll
        for (int t = 0; t < TH; t++) {
            float d = xv[t] - mean;
            var += d * d * mv[t];
        }
        var /= cnt;
        #pragma unroll
        for (int t = 0; t < TH - 1; t++)
            aug_s[w][t * 16 + f] = (xv[t + 1] - xv[t]) * mv[t + 1] * mv[t];
        aug_s[w][144 + f] = mean;
        aug_s[w][160 + f] = var;
    }
    __syncwarp();
    int i0 = 2 * lane;
    float acc0 = b1n[i0], acc1 = b1n[i0 + 1];
    for (int a = 0; a < 176; a++) {
        float av = aug_s[w][a];
        float2 wv = *reinterpret_cast<const float2*>(&W1n[(32 + a) * 64 + i0]);
        acc0 += av * wv.x;
        acc1 += av * wv.y;
    }
    g_augp[n * HH + i0]     = acc0;
    g_augp[n * HH + i0 + 1] = acc1;
}

// ---------------- per-stage: projection (one column per thread, 64 nodes/block) ----
__global__ void __launch_bounds__(192)
k_proj(const float* __restrict__ t_arr, const float* __restrict__ W1m,
       const float* __restrict__ W1n, const float* __restrict__ b1m,
       int stage, int step) {
    __shared__ __align__(16) float4 xi_s[64 * 4];
    int tid = threadIdx.x;
    int nb = blockIdx.x * 64;
    int nmax = NN - nb; if (nmax > 64) nmax = 64;

    int iv = step >> 2;
    float dt_int = (t_arr[iv + 1] - t_arr[iv]) * 0.25f;

    // ---- build xi (+ fused RK combine of previous step when stage==0) ----
    for (int i = tid; i < nmax * 4; i += 192) {
        int g = nb * 4 + i;
        float4 xv = g_x4[g];
        float4 out;
        if (stage == 0) {
            if (step > 0) {
                int pstep = step - 1;
                int piv = pstep >> 2;
                float pdt = (t_arr[piv + 1] - t_arr[piv]) * 0.25f;
                float4 s = make_float4(0.f, 0.f, 0.f, 0.f);
                s = f4fma(c_B[0], g_k4[0][g], s);
                s = f4fma(c_B[2], g_k4[2][g], s);
                s = f4fma(c_B[3], g_k4[3][g], s);
                s = f4fma(c_B[4], g_k4[4][g], s);
                s = f4fma(c_B[5], g_k4[5][g], s);
                out = f4fma(pdt, s, xv);
                g_x4[g] = out;
                if ((pstep & 3) == 3) g_ys4[piv][g] = out;
            } else {
                out = xv;
            }
        } else {
            float4 s = make_float4(0.f, 0.f, 0.f, 0.f);
            #pragma unroll
            for (int j = 0; j < 5; j++)
                if (j < stage) s = f4fma(c_A[stage][j], g_k4[j][g], s);
            out = f4fma(dt_int, s, xv);
        }
        xi_s[i] = out;
    }
    __syncthreads();

    // ---- one column per thread ----
    int col = tid & 63;
    int mat = tid >> 6;          // 0:U 1:V 2:W
    const float* wsrc;
    float* outp;
    float bias = 0.f;
    if (mat == 0)      { wsrc = W1m;           outp = g_U; }
    else if (mat == 1) { wsrc = W1m + 16 * 64; outp = g_V; bias = b1m[col]; }
    else               { wsrc = W1n;           outp = g_W; }
    float wreg[16];
    #pragma unroll
    for (int f = 0; f < 16; f++) wreg[f] = wsrc[f * 64 + col];

    for (int nl = 0; nl < nmax; nl++) {
        float4 a0 = xi_s[nl * 4 + 0];
        float4 a1 = xi_s[nl * 4 + 1];
        float4 a2 = xi_s[nl * 4 + 2];
        float4 a3 = xi_s[nl * 4 + 3];
        float acc = bias;
        acc = fmaf(a0.x, wreg[0],  acc); acc = fmaf(a0.y, wreg[1],  acc);
        acc = fmaf(a0.z, wreg[2],  acc); acc = fmaf(a0.w, wreg[3],  acc);
        acc = fmaf(a1.x, wreg[4],  acc); acc = fmaf(a1.y, wreg[5],  acc);
        acc = fmaf(a1.z, wreg[6],  acc); acc = fmaf(a1.w, wreg[7],  acc);
        acc = fmaf(a2.x, wreg[8],  acc); acc = fmaf(a2.y, wreg[9],  acc);
        acc = fmaf(a2.z, wreg[10], acc); acc = fmaf(a2.w, wreg[11], acc);
        acc = fmaf(a3.x, wreg[12], acc); acc = fmaf(a3.y, wreg[13], acc);
        acc = fmaf(a3.z, wreg[14], acc); acc = fmaf(a3.w, wreg[15], acc);
        outp[(nb + nl) * 64 + col] = acc;
    }
}

// ---------------- per-stage: edge aggregation + node MLP ----------------
__global__ void __launch_bounds__(256)
k_node(const float* __restrict__ t_arr, const float* __restrict__ W1m,
       const float* __restrict__ W1n, const float* __restrict__ W2n,
       const float* __restrict__ b2n, int stage, int step) {
    __shared__ float M_s[HH * HH];           // [j*64 + c]
    __shared__ float W2t[16][68];            // transposed W2n, padded
    __shared__ float wt_s[64], c_s[64];
    __shared__ float b2n_s[16];
    __shared__ __align__(16) float hbuf[8][64];

    int tid = threadIdx.x, lane = tid & 31, w = tid >> 5;
    for (int i = tid; i < HH * HH; i += 256) M_s[i] = g_M[i];
    for (int i = tid; i < 1024; i += 256) W2t[i & 15][i >> 4] = W2n[i];
    for (int i = tid; i < 64; i += 256) { wt_s[i] = W1n[208 * 64 + i]; c_s[i] = g_c[i]; }
    if (tid < 16) b2n_s[tid] = b2n[tid];
    __syncthreads();

    int iv = step >> 2;
    float dt_int = (t_arr[iv + 1] - t_arr[iv]) * 0.25f;
    float ti = t_arr[iv] + (float)(step & 3) * dt_int + c_C[stage] * dt_int;

    float2 wc0 = *reinterpret_cast<const float2*>(&W1m[32 * 64 + 2 * lane]);
    float2 wc1 = *reinterpret_cast<const float2*>(&W1m[33 * 64 + 2 * lane]);
    float2 wc2 = *reinterpret_cast<const float2*>(&W1m[34 * 64 + 2 * lane]);
    float2 wc3 = *reinterpret_cast<const float2*>(&W1m[35 * 64 + 2 * lane]);

    for (int rep = 0; rep < 8; rep++) {
        int n = blockIdx.x * 64 + rep * 8 + w;
        if (n >= NN) continue;   // warp-uniform
        int rs = g_rowptr[n], re = g_rowptr[n + 1];
        float2 vv = *reinterpret_cast<const float2*>(&g_V[n * 64 + 2 * lane]);
        float hs0 = 0.f, hs1 = 0.f;

        for (int base = rs; base < re; base += 32) {
            int rem = re - base;
            int cnt = rem < 32 ? rem : 32;
            int sv = __ldg(&g_srcs[base + (lane < cnt ? lane : cnt - 1)]);
            for (int j0 = 0; j0 < cnt; j0 += 4) {
                int l1 = j0 + 1 < cnt ? j0 + 1 : cnt - 1;
                int l2 = j0 + 2 < cnt ? j0 + 2 : cnt - 1;
                int l3 = j0 + 3 < cnt ? j0 + 3 : cnt - 1;
                int s0 = __shfl_sync(0xffffffffu, sv, j0);
                int s1 = __shfl_sync(0xffffffffu, sv, l1);
                int s2 = __shfl_sync(0xffffffffu, sv, l2);
                int s3 = __shfl_sync(0xffffffffu, sv, l3);
                float2 u0 = *reinterpret_cast<const float2*>(&g_U[s0 * 64 + 2 * lane]);
                float2 u1 = *reinterpret_cast<const float2*>(&g_U[s1 * 64 + 2 * lane]);
                float2 u2 = *reinterpret_cast<const float2*>(&g_U[s2 * 64 + 2 * lane]);
                float2 u3 = *reinterpret_cast<const float2*>(&g_U[s3 * 64 + 2 * lane]);
                float4 e0 = g_eas[base + j0];
                float4 e1 = g_eas[base + l1];
                float4 e2 = g_eas[base + l2];
                float4 e3 = g_eas[base + l3];
                float m1 = (j0 + 1 < cnt) ? 1.f : 0.f;
                float m2 = (j0 + 2 < cnt) ? 1.f : 0.f;
                float m3 = (j0 + 3 < cnt) ? 1.f : 0.f;

                float p;
                p = u0.x + vv.x; p = fmaf(e0.x, wc0.x, p); p = fmaf(e0.y, wc1.x, p);
                p = fmaf(e0.z, wc2.x, p); p = fmaf(e0.w, wc3.x, p);
                hs0 += tanha(p);
                p = u0.y + vv.y; p = fmaf(e0.x, wc0.y, p); p = fmaf(e0.y, wc1.y, p);
                p = fmaf(e0.z, wc2.y, p); p = fmaf(e0.w, wc3.y, p);
                hs1 += tanha(p);

                p = u1.x + vv.x; p = fmaf(e1.x, wc0.x, p); p = fmaf(e1.y, wc1.x, p);
                p = fmaf(e1.z, wc2.x, p); p = fmaf(e1.w, wc3.x, p);
                hs0 = fmaf(m1, tanha(p), hs0);
                p = u1.y + vv.y; p = fmaf(e1.x, wc0.y, p); p = fmaf(e1.y, wc1.y, p);
                p = fmaf(e1.z, wc2.y, p); p = fmaf(e1.w, wc3.y, p);
                hs1 = fmaf(m1, tanha(p), hs1);

                p = u2.x + vv.x; p = fmaf(e2.x, wc0.x, p); p = fmaf(e2.y, wc1.x, p);
                p = fmaf(e2.z, wc2.x, p); p = fmaf(e2.w, wc3.x, p);
                hs0 = fmaf(m2, tanha(p), hs0);
                p = u2.y + vv.y; p = fmaf(e2.x, wc0.y, p); p = fmaf(e2.y, wc1.y, p);
                p = fmaf(e2.z, wc2.y, p); p = fmaf(e2.w, wc3.y, p);
                hs1 = fmaf(m2, tanha(p), hs1);

                p = u3.x + vv.x; p = fmaf(e3.x, wc0.x, p); p = fmaf(e3.y, wc1.x, p);
                p = fmaf(e3.z, wc2.x, p); p = fmaf(e3.w, wc3.x, p);
                hs0 = fmaf(m3, tanha(p), hs0);
                p = u3.y + vv.y; p = fmaf(e3.x, wc0.y, p); p = fmaf(e3.y, wc1.y, p);
                p = fmaf(e3.z, wc2.y, p); p = fmaf(e3.w, wc3.y, p);
                hs1 = fmaf(m3, tanha(p), hs1);
            }
        }

        hbuf[w][2 * lane] = hs0; hbuf[w][2 * lane + 1] = hs1;
        __syncwarp();

        float deg = (float)(re - rs);
        float2 ww = *reinterpret_cast<const float2*>(&g_W[n * 64 + 2 * lane]);
        float2 ap = *reinterpret_cast<const float2*>(&g_augp[n * HH + 2 * lane]);
        float a0 = ww.x + deg * c_s[2 * lane]     + ti * wt_s[2 * lane]     + ap.x;
        float a1 = ww.y + deg * c_s[2 * lane + 1] + ti * wt_s[2 * lane + 1] + ap.y;

        const float4* h4 = reinterpret_cast<const float4*>(hbuf[w]);
        #pragma unroll
        for (int jj = 0; jj < 16; jj++) {
            float4 hv = h4[jj];
            int j = jj * 4;
            float2 m0 = *reinterpret_cast<const float2*>(&M_s[(j + 0) * 64 + 2 * lane]);
            float2 m1 = *reinterpret_cast<const float2*>(&M_s[(j + 1) * 64 + 2 * lane]);
            float2 m2 = *reinterpret_cast<const float2*>(&M_s[(j + 2) * 64 + 2 * lane]);
            float2 m3 = *reinterpret_cast<const float2*>(&M_s[(j + 3) * 64 + 2 * lane]);
            a0 = fmaf(hv.x, m0.x, a0); a1 = fmaf(hv.x, m0.y, a1);
            a0 = fmaf(hv.y, m1.x, a0); a1 = fmaf(hv.y, m1.y, a1);
            a0 = fmaf(hv.z, m2.x, a0); a1 = fmaf(hv.z, m2.y, a1);
            a0 = fmaf(hv.w, m3.x, a0); a1 = fmaf(hv.w, m3.y, a1);
        }
        float h20 = tanh_fast(a0), h21 = tanh_fast(a1);
        __syncwarp();
        hbuf[w][2 * lane] = h20; hbuf[w][2 * lane + 1] = h21;
        __syncwarp();

        // 64x16 output matmul: split j-range, shfl reduce
        {
            int colc = lane & 15;
            int j0 = (lane >> 4) * 32;
            const float4* hh = reinterpret_cast<const float4*>(&hbuf[w][j0]);
            float acc = 0.f;
            #pragma unroll
            for (int q = 0; q < 8; q++) {
                float4 hv = hh[q];
                float4 wv = *reinterpret_cast<const float4*>(&W2t[colc][j0 + q * 4]);
                acc = fmaf(hv.x, wv.x, acc); acc = fmaf(hv.y, wv.y, acc);
                acc = fmaf(hv.z, wv.z, acc); acc = fmaf(hv.w, wv.w, acc);
            }
            acc += __shfl_xor_sync(0xffffffffu, acc, 16);
            if (lane < 16)
                reinterpret_cast<float*>(g_k4[stage])[n * 16 + lane] = acc + b2n_s[lane];
        }
        __syncwarp();
    }
}

__global__ void k_combine_final(const float* __restrict__ t_arr, int step) {
    int g = blockIdx.x * blockDim.x + threadIdx.x;
    if (g >= NF4) return;
    int iv = step >> 2;
    float dt_int = (t_arr[iv + 1] - t_arr[iv]) * 0.25f;
    float4 s = make_float4(0.f, 0.f, 0.f, 0.f);
    s = f4fma(c_B[0], g_k4[0][g], s);
    s = f4fma(c_B[2], g_k4[2][g], s);
    s = f4fma(c_B[3], g_k4[3][g], s);
    s = f4fma(c_B[4], g_k4[4][g], s);
    s = f4fma(c_B[5], g_k4[5][g], s);
    float4 xn = f4fma(dt_int, s, g_x4[g]);
    g_x4[g] = xn;
    if ((step & 3) == 3) g_ys4[iv][g] = xn;
}

__global__ void k_out(const int* __restrict__ midx, float4* __restrict__ out) {
    int idx = blockIdx.x * blockDim.x + threadIdx.x;
    if (idx >= TOUT * NF4) return;
    int r = idx / NF4;
    out[idx] = g_ys4[midx[r]][idx - r * NF4];
}

// ---------------- launch ----------------
extern "C" void kernel_launch(void* const* d_in, const int* in_sizes, int n_in,
                              void* d_out, int out_size) {
    const float* x_hist = (const float*)d_in[0];
    const float* x_mask = (const float*)d_in[1];
    const int*   eidx   = (const int*)  d_in[2];
    const float* eattr  = (const float*)d_in[3];
    const float* t_arr  = (const float*)d_in[4];
    const int*   midx   = (const int*)  d_in[5];
    const float* W1m = (const float*)d_in[6];
    const float* b1m = (const float*)d_in[7];
    const float* W2m = (const float*)d_in[8];
    const float* b2m = (const float*)d_in[9];
    const float* W1n = (const float*)d_in[10];
    const float* b1n = (const float*)d_in[11];
    const float* W2n = (const float*)d_in[12];
    const float* b2n = (const float*)d_in[13];
    float4* out = (float4*)d_out;

    k_zero   <<<(NN + 255) / 256, 256>>>();
    k_hist   <<<(EE + 255) / 256, 256>>>(eidx);
    k_scan   <<<1, 1024>>>();
    k_scatter<<<(EE + 255) / 256, 256>>>(eidx, eattr);
    k_init_x <<<(NF4 + 255) / 256, 256>>>(x_hist);
    k_M      <<<(HH * HH + 255) / 256, 256>>>(W2m, W1n, b2m);
    k_aug    <<<(NN + 7) / 8, 256>>>(x_hist, x_mask, W1n, b1n);

    for (int step = 0; step < NSTEPS; step++) {
        for (int stage = 0; stage < 6; stage++) {
            k_proj<<<(NN + 63) / 64, 192>>>(t_arr, W1m, W1n, b1m, stage, step);
            k_node<<<(NN + 63) / 64, 256>>>(t_arr, W1m, W1n, W2n, b2n, stage, step);
        }
    }
    k_combine_final<<<(NF4 + 255) / 256, 256>>>(t_arr, NSTEPS - 1);
    k_out<<<(TOUT * NF4 + 255) / 256, 256>>>(midx, out);
}